// round 15
// baseline (speedup 1.0000x reference)
#include <cuda_runtime.h>
#include <cuda_bf16.h>
#include <cuda_fp16.h>
#include <cstdint>

#define HIDDEN 192
#define MAXDEG 32
#define MAX_S 8192
#define MAX_E (MAX_S * MAXDEG)

// scratch (device globals: allocation-free). 16B-aligned for vector ld/st + cp.async.
__device__ __align__(16) float g_dstpart[MAX_S * HIDDEN];         // b1 + x_dst @ W1_bot
__device__ __align__(16) float g_pooled[MAX_S * HIDDEN];          // mean(gelu(...))
__device__ __align__(16) __half g_Aemb[(size_t)MAX_E * HIDDEN];   // src edge embeds fp16
__device__ __align__(16) __half g_W1Tf16[HIDDEN * HIDDEN];        // W1_top^T fp16 [n][k]
__device__ __align__(16) __nv_bfloat16 g_W1bThi[HIDDEN * HIDDEN]; // W1_bot^T hi
__device__ __align__(16) __nv_bfloat16 g_W1bTlo[HIDDEN * HIDDEN]; // W1_bot^T lo
__device__ __align__(16) __nv_bfloat16 g_W2Thi[HIDDEN * HIDDEN];  // W2^T hi
__device__ __align__(16) __nv_bfloat16 g_W2Tlo[HIDDEN * HIDDEN];  // W2^T lo

// ---------------- helpers ----------------
__device__ __forceinline__ float sin_poly(float x) {
    float x2 = x * x;
    float p = -1.98412698e-4f;
    p = fmaf(p, x2, 8.33333333e-3f);
    p = fmaf(p, x2, -1.66666667e-1f);
    return fmaf(x * x2, p, x);
}
__device__ __forceinline__ float cos_poly(float x) {
    float x2 = x * x;
    float p = 2.48015873e-5f;
    p = fmaf(p, x2, -1.38888889e-3f);
    p = fmaf(p, x2, 4.16666667e-2f);
    p = fmaf(p, x2, -0.5f);
    return fmaf(p, x2, 1.0f);
}
// branch-free GELU: A&S 7.1.26 erf (abs err <= 1.5e-7), MUFU rcp/ex2
__device__ __forceinline__ float gelu_fast(float x) {
    float z = fabsf(x) * 0.7071067811865476f;
    float d = fmaf(0.3275911f, z, 1.0f);
    float t;
    asm("rcp.approx.f32 %0, %1;" : "=f"(t) : "f"(d));
    float p = 1.061405429f;
    p = fmaf(p, t, -1.453152027f);
    p = fmaf(p, t, 1.421413741f);
    p = fmaf(p, t, -0.284496736f);
    p = fmaf(p, t, 0.254829592f);
    p = p * t;
    float y = -1.4426950408889634f * z * z;
    float e;
    asm("ex2.approx.f32 %0, %1;" : "=f"(e) : "f"(y));
    float erfv = fmaf(-p, e, 1.0f);
    erfv = copysignf(erfv, x);
    float hx = 0.5f * x;
    return fmaf(hx, erfv, hx);
}
__device__ __forceinline__ float embed_channel(int c, float f0, float f1, float f2,
                                               const float* pp, const float* sWin,
                                               const float* sBin, const float* sOmega) {
    float v = sBin[c];
    v = fmaf(f0, sWin[c], v);
    v = fmaf(f1, sWin[HIDDEN + c], v);
    v = fmaf(f2, sWin[2 * HIDDEN + c], v);
    int axis = c >> 6;
    int j = c & 63;
    float ang = pp[axis] * sOmega[j & 31];
    float e = (j < 32) ? sin_poly(ang) : cos_poly(ang);
    return v + e;
}
__device__ __forceinline__ void mma_bf16(float* c, uint32_t a0, uint32_t a1, uint32_t a2,
                                         uint32_t a3, uint32_t b0, uint32_t b1) {
    asm volatile(
        "mma.sync.aligned.m16n8k16.row.col.f32.bf16.bf16.f32 "
        "{%0,%1,%2,%3}, {%4,%5,%6,%7}, {%8,%9}, {%0,%1,%2,%3};"
        : "+f"(c[0]), "+f"(c[1]), "+f"(c[2]), "+f"(c[3])
        : "r"(a0), "r"(a1), "r"(a2), "r"(a3), "r"(b0), "r"(b1));
}
__device__ __forceinline__ void mma_f16(float* c, uint32_t a0, uint32_t a1, uint32_t a2,
                                        uint32_t a3, uint32_t b0, uint32_t b1) {
    asm volatile(
        "mma.sync.aligned.m16n8k16.row.col.f32.f16.f16.f32 "
        "{%0,%1,%2,%3}, {%4,%5,%6,%7}, {%8,%9}, {%0,%1,%2,%3};"
        : "+f"(c[0]), "+f"(c[1]), "+f"(c[2]), "+f"(c[3])
        : "r"(a0), "r"(a1), "r"(a2), "r"(a3), "r"(b0), "r"(b1));
}
__device__ __forceinline__ void ldsm_x4(uint32_t& r0, uint32_t& r1, uint32_t& r2,
                                        uint32_t& r3, uint32_t addr) {
    asm volatile("ldmatrix.sync.aligned.m8n8.x4.shared.b16 {%0,%1,%2,%3}, [%4];"
                 : "=r"(r0), "=r"(r1), "=r"(r2), "=r"(r3) : "r"(addr));
}
__device__ __forceinline__ uint32_t pack_bf16(float v0, float v1) {
    __nv_bfloat162 t;
    t.x = __float2bfloat16(v0);
    t.y = __float2bfloat16(v1);
    return *reinterpret_cast<uint32_t*>(&t);
}
__device__ __forceinline__ uint32_t pack_f16(float v0, float v1) {
    __half2 t;
    t.x = __float2half_rn(v0);
    t.y = __float2half_rn(v1);
    return *reinterpret_cast<uint32_t*>(&t);
}
__device__ __forceinline__ uint32_t smem_u32(const void* p) {
    uint32_t a;
    asm("{ .reg .u64 t; cvta.to.shared.u64 t, %1; cvt.u32.u64 %0, t; }" : "=r"(a) : "l"(p));
    return a;
}
__device__ __forceinline__ void cp_async16(void* dst_smem, const void* src) {
    uint32_t d = smem_u32(dst_smem);
    asm volatile("cp.async.cg.shared.global [%0], [%1], 16;" :: "r"(d), "l"(src) : "memory");
}
__device__ __forceinline__ void cp_async_commit() {
    asm volatile("cp.async.commit_group;" ::: "memory");
}
__device__ __forceinline__ void cp_async_wait0() {
    asm volatile("cp.async.wait_group 0;" ::: "memory");
}

#define STRIDE_A 80
#define STRIDE_B 80

__device__ __forceinline__ uint32_t b_lane_off(int wn, int lane, int nw) {
    return (uint32_t)(wn * nw + ((lane >> 4) & 1) * 8 + (lane & 7)) * STRIDE_B +
           ((lane >> 3) & 1) * 16;
}
__device__ __forceinline__ uint32_t a_lane_off(int wm, int lane) {
    return (uint32_t)(wm * 16 + (lane & 15)) * STRIDE_A + ((lane >> 4) & 1) * 16;
}

#define CONSUME_3T(NP, aHiL, aLoL, bHiA, bLoA)                                           \
    _Pragma("unroll") for (int ks = 0; ks < 2; ++ks) {                                   \
        uint32_t ah0, ah1, ah2, ah3, al0, al1, al2, al3;                                 \
        ldsm_x4(ah0, ah1, ah2, ah3, (aHiL) + ks * 32);                                   \
        ldsm_x4(al0, al1, al2, al3, (aLoL) + ks * 32);                                   \
        _Pragma("unroll") for (int p = 0; p < (NP); ++p) {                               \
            uint32_t bh0, bh1, bh2, bh3, bl0, bl1, bl2, bl3;                             \
            ldsm_x4(bh0, bh1, bh2, bh3, (bHiA) + p * (16 * STRIDE_B) + ks * 32);         \
            ldsm_x4(bl0, bl1, bl2, bl3, (bLoA) + p * (16 * STRIDE_B) + ks * 32);         \
            mma_bf16(acc[2 * p], ah0, ah1, ah2, ah3, bh0, bh1);                          \
            mma_bf16(acc[2 * p], al0, al1, al2, al3, bh0, bh1);                          \
            mma_bf16(acc[2 * p], ah0, ah1, ah2, ah3, bl0, bl1);                          \
            mma_bf16(acc[2 * p + 1], ah0, ah1, ah2, ah3, bh2, bh3);                      \
            mma_bf16(acc[2 * p + 1], al0, al1, al2, al3, bh2, bh3);                      \
            mma_bf16(acc[2 * p + 1], ah0, ah1, ah2, ah3, bl2, bl3);                      \
        }                                                                                \
    }

#define CONSUME_1T(NP, aHiL, bHiA)                                                       \
    _Pragma("unroll") for (int ks = 0; ks < 2; ++ks) {                                   \
        uint32_t ah0, ah1, ah2, ah3;                                                     \
        ldsm_x4(ah0, ah1, ah2, ah3, (aHiL) + ks * 32);                                   \
        _Pragma("unroll") for (int p = 0; p < (NP); ++p) {                               \
            uint32_t bh0, bh1, bh2, bh3;                                                 \
            ldsm_x4(bh0, bh1, bh2, bh3, (bHiA) + p * (16 * STRIDE_B) + ks * 32);         \
            mma_f16(acc[2 * p], ah0, ah1, ah2, ah3, bh0, bh1);                           \
            mma_f16(acc[2 * p + 1], ah0, ah1, ah2, ah3, bh2, bh3);                       \
        }                                                                                \
    }

// ============================================================
// Kernel P: W1_top^T -> fp16; W1_bot^T, W2^T -> bf16 hi/lo
// ============================================================
__global__ void __launch_bounds__(256)
weight_split_kernel(const float* __restrict__ W1, const float* __restrict__ W2) {
    int i = blockIdx.x * 256 + threadIdx.x;
    if (i >= HIDDEN * HIDDEN) return;
    int k = i / HIDDEN, n = i % HIDDEN;
    g_W1Tf16[n * HIDDEN + k] = __float2half_rn(W1[k * HIDDEN + n]);
    {
        float w = W1[(HIDDEN + k) * HIDDEN + n];
        __nv_bfloat16 hi = __float2bfloat16(w);
        g_W1bThi[n * HIDDEN + k] = hi;
        g_W1bTlo[n * HIDDEN + k] = __float2bfloat16(w - __bfloat162float(hi));
    }
    {
        float w = W2[k * HIDDEN + n];
        __nv_bfloat16 hi = __float2bfloat16(w);
        g_W2Thi[n * HIDDEN + k] = hi;
        g_W2Tlo[n * HIDDEN + k] = __float2bfloat16(w - __bfloat162float(hi));
    }
}

// ============================================================
// Kernel E: precompute src edge embeddings -> g_Aemb fp16
// 8 threads per edge, 24 channels each; coalesced 16B stores.
// ============================================================
__global__ void __launch_bounds__(256)
embed_kernel(const float* __restrict__ feat, const float* __restrict__ pos,
             const int* __restrict__ src_idx, const float* __restrict__ Win,
             const float* __restrict__ bin, int E) {
    __shared__ float sWin[3 * HIDDEN], sBin[HIDDEN], sOmega[32];
    const int tid = threadIdx.x;
    for (int i = tid; i < 3 * HIDDEN; i += 256) sWin[i] = Win[i];
    for (int i = tid; i < HIDDEN; i += 256) sBin[i] = bin[i];
    if (tid < 32) sOmega[tid] = exp2f(-(float)tid * 0.4152410118609203f);
    __syncthreads();

    int gid = blockIdx.x * 256 + tid;
    int e = gid >> 3;
    int s = gid & 7;
    if (e >= E) return;

    int node = src_idx[e];
    float f0 = feat[node * 3], f1 = feat[node * 3 + 1], f2 = feat[node * 3 + 2];
    float pp[3] = {pos[node * 3], pos[node * 3 + 1], pos[node * 3 + 2]};

    uint32_t buf[12];
#pragma unroll
    for (int i = 0; i < 24; i += 2) {
        int c = s * 24 + i;
        float v0 = embed_channel(c, f0, f1, f2, pp, sWin, sBin, sOmega);
        float v1 = embed_channel(c + 1, f0, f1, f2, pp, sWin, sBin, sOmega);
        buf[i >> 1] = pack_f16(v0, v1);
    }
    uint4* dst = reinterpret_cast<uint4*>(g_Aemb + (size_t)e * HIDDEN + s * 24);
#pragma unroll
    for (int j = 0; j < 3; ++j)
        dst[j] = make_uint4(buf[j * 4], buf[j * 4 + 1], buf[j * 4 + 2], buf[j * 4 + 3]);
}

// ============================================================
// Kernels A/C: M=32/CTA, 256 thr, bf16 3-term, PIPELINED (R14)
// ============================================================
#define XAB (32 * STRIDE_A)
#define XBB (HIDDEN * STRIDE_B)
#define XOFF_AHI 0
#define XOFF_ALO (2 * XAB)
#define XOFF_BHI (4 * XAB)
#define XOFF_BLO (4 * XAB + 2 * XBB)
#define XOFF_CONST (4 * XAB + 4 * XBB)
#define XSMEM_DST (XOFF_CONST + 3 * HIDDEN * 4 + HIDDEN * 4 + 128 + HIDDEN * 4)
#define XSMEM_OUT (XOFF_CONST + HIDDEN * 4)

__device__ __forceinline__ void aux_copy_B_async(unsigned char* sm, int buf, int ch,
                                                 int tid, const __nv_bfloat16* Whi,
                                                 const __nv_bfloat16* Wlo) {
#pragma unroll
    for (int i = 0; i < 6; ++i) {
        int isLo = i >= 3;
        int id = tid + 256 * (isLo ? (i - 3) : i);
        int n = id >> 2, seg = id & 3;
        const __nv_bfloat16* src =
            (isLo ? Wlo : Whi) + n * HIDDEN + ch * 32 + seg * 8;
        unsigned char* dst = sm + (isLo ? XOFF_BLO : XOFF_BHI) + buf * XBB +
                             n * STRIDE_B + seg * 16;
        cp_async16(dst, src);
    }
}

__global__ void __launch_bounds__(256, 2)
dst_mma_kernel(const float* __restrict__ feat, const float* __restrict__ pos,
               const int* __restrict__ dst_idx, const float* __restrict__ Win,
               const float* __restrict__ bin, const float* __restrict__ b1) {
    extern __shared__ __align__(16) unsigned char sm[];
    float* sWin = (float*)(sm + XOFF_CONST);
    float* sBin = (float*)(sm + XOFF_CONST + 3 * HIDDEN * 4);
    float* sOmega = (float*)(sm + XOFF_CONST + 4 * HIDDEN * 4);
    float* sB1 = (float*)(sm + XOFF_CONST + 4 * HIDDEN * 4 + 128);

    const int tid = threadIdx.x;
    const int lane = tid & 31;
    const int w = tid >> 5;
    const int wm = w & 1, wn = w >> 1;
    const int g = lane >> 2, tg = lane & 3;
    const int s0 = blockIdx.x * 32;

    for (int i = tid; i < 3 * HIDDEN; i += 256) sWin[i] = Win[i];
    for (int i = tid; i < HIDDEN; i += 256) sBin[i] = bin[i];
    for (int i = tid; i < HIDDEN; i += 256) sB1[i] = b1[i];
    if (tid < 32) sOmega[tid] = exp2f(-(float)tid * 0.4152410118609203f);

    const int m = tid & 31;
    const int jb = (tid >> 5) * 4;
    int node = dst_idx[(s0 + m) * MAXDEG];
    float f0 = feat[node * 3], f1 = feat[node * 3 + 1], f2 = feat[node * 3 + 2];
    float pp[3] = {pos[node * 3], pos[node * 3 + 1], pos[node * 3 + 2]};
    __syncthreads();

    float acc[6][4];
#pragma unroll
    for (int i = 0; i < 6; ++i)
#pragma unroll
        for (int j = 0; j < 4; ++j) acc[i][j] = 0.0f;

    const uint32_t smB = smem_u32(sm);
    const uint32_t aLane = a_lane_off(wm, lane);
    const uint32_t bLane = b_lane_off(wn, lane, 48);

#define DST_PRODUCE_A(buf, ch)                                                           \
    _Pragma("unroll") for (int j = 0; j < 4; j += 2) {                                   \
        int c0 = (ch) * 32 + jb + j;                                                     \
        float v0 = embed_channel(c0, f0, f1, f2, pp, sWin, sBin, sOmega);                \
        float v1 = embed_channel(c0 + 1, f0, f1, f2, pp, sWin, sBin, sOmega);            \
        __nv_bfloat16 h0 = __float2bfloat16(v0);                                         \
        __nv_bfloat16 h1 = __float2bfloat16(v1);                                         \
        float l0 = v0 - __bfloat162float(h0);                                            \
        float l1 = v1 - __bfloat162float(h1);                                            \
        __nv_bfloat162 hp; hp.x = h0; hp.y = h1;                                         \
        *(uint32_t*)(sm + XOFF_AHI + (buf) * XAB + m * STRIDE_A + (jb + j) * 2) =        \
            *reinterpret_cast<uint32_t*>(&hp);                                           \
        *(uint32_t*)(sm + XOFF_ALO + (buf) * XAB + m * STRIDE_A + (jb + j) * 2) =        \
            pack_bf16(l0, l1);                                                           \
    }

    DST_PRODUCE_A(0, 0)
    aux_copy_B_async(sm, 0, 0, tid, g_W1bThi, g_W1bTlo);
    cp_async_commit();
    cp_async_wait0();
    __syncthreads();

    for (int ch = 0; ch < 6; ++ch) {
        const int cur = ch & 1;
        const int nxt = (ch + 1) & 1;
        if (ch < 5) {
            DST_PRODUCE_A(nxt, ch + 1)
            aux_copy_B_async(sm, nxt, ch + 1, tid, g_W1bThi, g_W1bTlo);
            cp_async_commit();
        }
        const uint32_t aHiL = smB + XOFF_AHI + cur * XAB + aLane;
        const uint32_t aLoL = smB + XOFF_ALO + cur * XAB + aLane;
        const uint32_t bHiA = smB + XOFF_BHI + cur * XBB + bLane;
        const uint32_t bLoA = smB + XOFF_BLO + cur * XBB + bLane;
        CONSUME_3T(3, aHiL, aLoL, bHiA, bLoA)
        if (ch < 5) cp_async_wait0();
        __syncthreads();
    }

    const int r_hi = s0 + wm * 16 + g;
#pragma unroll
    for (int in = 0; in < 6; ++in) {
        int c = wn * 48 + in * 8 + tg * 2;
        float2 bb = *(const float2*)&sB1[c];
        float2 v0 = {acc[in][0] + bb.x, acc[in][1] + bb.y};
        float2 v1 = {acc[in][2] + bb.x, acc[in][3] + bb.y};
        *(float2*)&g_dstpart[r_hi * HIDDEN + c] = v0;
        *(float2*)&g_dstpart[(r_hi + 8) * HIDDEN + c] = v1;
    }
}

// ============================================================
// Kernel B: snp_mma — lean GEMM. A from g_Aemb via cp.async,
// fp16 1-term, 512 threads/16 warps, occ 2.
// ============================================================
#define AB (64 * STRIDE_A)        // 5120
#define BBUF (HIDDEN * STRIDE_B)  // 15360
#define OFF_AHI 0
#define OFF_BHI (2 * AB)
#define OFF_DST (2 * AB + 2 * BBUF)
#define OFF_COL (OFF_DST + 2 * HIDDEN * 4)
#define SMEMB_TOTAL (OFF_COL + 4 * HIDDEN * 4)   // 45568

// per chunk: B 768 segs + A 256 segs over 512 threads (2 each)
__device__ __forceinline__ void copy_AB(unsigned char* sm, int bufA, int bufB, int b,
                                        int ch, int tid) {
    {
        int n = tid >> 2, seg = tid & 3;
        cp_async16(sm + OFF_BHI + bufB * BBUF + n * STRIDE_B + seg * 16,
                   g_W1Tf16 + n * HIDDEN + ch * 32 + seg * 8);
    }
    if (tid < 256) {
        int id = tid + 512;
        int n = id >> 2, seg = id & 3;
        cp_async16(sm + OFF_BHI + bufB * BBUF + n * STRIDE_B + seg * 16,
                   g_W1Tf16 + n * HIDDEN + ch * 32 + seg * 8);
    } else {
        int id = tid - 256;
        int m = id >> 2, seg = id & 3;
        cp_async16(sm + OFF_AHI + bufA * AB + m * STRIDE_A + seg * 16,
                   g_Aemb + (size_t)(b * 64 + m) * HIDDEN + ch * 32 + seg * 8);
    }
}

__global__ void __launch_bounds__(512, 2)
snp_mma_kernel() {
    extern __shared__ __align__(16) unsigned char sm[];
    float* sDst = (float*)(sm + OFF_DST);
    float* sCol = (float*)(sm + OFF_COL);

    const int b = blockIdx.x;
    const int tid = threadIdx.x;
    const int lane = tid & 31;
    const int w = tid >> 5;
    const int wm = w & 3, wn = w >> 2;
    const int g = lane >> 2, tg = lane & 3;

    for (int i = tid; i < 2 * HIDDEN; i += 512) sDst[i] = g_dstpart[b * 2 * HIDDEN + i];

    float acc[6][4];
#pragma unroll
    for (int i = 0; i < 6; ++i)
#pragma unroll
        for (int j = 0; j < 4; ++j) acc[i][j] = 0.0f;

    const uint32_t smB = smem_u32(sm);
    const uint32_t aLane = a_lane_off(wm, lane);
    const uint32_t bLane = b_lane_off(wn, lane, 48);

    copy_AB(sm, 0, 0, b, 0, tid);
    cp_async_commit();
    cp_async_wait0();
    __syncthreads();

    for (int c = 0; c < 6; ++c) {
        const int cur = c & 1;
        const int nxt = (c + 1) & 1;
        if (c < 5) {
            copy_AB(sm, nxt, nxt, b, c + 1, tid);
            cp_async_commit();
        }

        const uint32_t aHiL = smB + OFF_AHI + cur * AB + aLane;
        const uint32_t bHiA = smB + OFF_BHI + cur * BBUF + bLane;
        CONSUME_1T(3, aHiL, bHiA)

        if (c < 5) cp_async_wait0();
        __syncthreads();
    }

    // epilogue: + dstpart, fast GELU, column sums
    const int sn = wm >> 1;
#pragma unroll
    for (int in = 0; in < 6; ++in) {
        int c = wn * 48 + in * 8 + tg * 2;
        float2 d = *(const float2*)&sDst[sn * HIDDEN + c];
        float t0 = gelu_fast(acc[in][0] + d.x) + gelu_fast(acc[in][2] + d.x);
        float t1 = gelu_fast(acc[in][1] + d.y) + gelu_fast(acc[in][3] + d.y);
#pragma unroll
        for (int off = 4; off < 32; off <<= 1) {
            t0 += __shfl_xor_sync(0xffffffffu, t0, off);
            t1 += __shfl_xor_sync(0xffffffffu, t1, off);
        }
        if (lane < 4) {
            sCol[wm * HIDDEN + c] = t0;
            sCol[wm * HIDDEN + c + 1] = t1;
        }
    }
    __syncthreads();
    for (int i = tid; i < 2 * HIDDEN; i += 512) {
        int s = i / HIDDEN, n = i % HIDDEN;
        g_pooled[(b * 2 + s) * HIDDEN + n] =
            (sCol[s * 2 * HIDDEN + n] + sCol[(s * 2 + 1) * HIDDEN + n]) * (1.0f / 32.0f);
    }
}

// ============================================================
// Kernel C: out = g_pooled @ W2 + b2, M=32/CTA, PIPELINED (R14)
// ============================================================
__global__ void __launch_bounds__(256, 2)
out_mma_kernel(const float* __restrict__ b2, float* __restrict__ out) {
    extern __shared__ __align__(16) unsigned char sm[];
    float* sB2 = (float*)(sm + XOFF_CONST);

    const int tid = threadIdx.x;
    const int lane = tid & 31;
    const int w = tid >> 5;
    const int wm = w & 1, wn = w >> 1;
    const int g = lane >> 2, tg = lane & 3;
    const int s0 = blockIdx.x * 32;

    for (int i = tid; i < HIDDEN; i += 256) sB2[i] = b2[i];

    const int m = tid & 31;
    const int jb = (tid >> 5) * 4;

    float acc[6][4];
#pragma unroll
    for (int i = 0; i < 6; ++i)
#pragma unroll
        for (int j = 0; j < 4; ++j) acc[i][j] = 0.0f;

    const uint32_t smB = smem_u32(sm);
    const uint32_t aLane = a_lane_off(wm, lane);
    const uint32_t bLane = b_lane_off(wn, lane, 48);

#define OUT_PRODUCE_A(buf, ch)                                                           \
    {                                                                                    \
        const float* arow = g_pooled + (s0 + m) * HIDDEN + (ch) * 32 + jb;               \
        _Pragma("unroll") for (int j = 0; j < 4; j += 2) {                               \
            float2 v = *(const float2*)&arow[j];                                         \
            __nv_bfloat16 h0 = __float2bfloat16(v.x);                                    \
            __nv_bfloat16 h1 = __float2bfloat16(v.y);                                    \
            float l0 = v.x - __bfloat162float(h0);                                       \
            float l1 = v.y - __bfloat162float(h1);                                       \
            __nv_bfloat162 hp; hp.x = h0; hp.y = h1;                                     \
            *(uint32_t*)(sm + XOFF_AHI + (buf) * XAB + m * STRIDE_A + (jb + j) * 2) =    \
                *reinterpret_cast<uint32_t*>(&hp);                                       \
            *(uint32_t*)(sm + XOFF_ALO + (buf) * XAB + m * STRIDE_A + (jb + j) * 2) =    \
                pack_bf16(l0, l1);                                                       \
        }                                                                                \
    }

    OUT_PRODUCE_A(0, 0)
    aux_copy_B_async(sm, 0, 0, tid, g_W2Thi, g_W2Tlo);
    cp_async_commit();
    cp_async_wait0();
    __syncthreads();

    for (int ch = 0; ch < 6; ++ch) {
        const int cur = ch & 1;
        const int nxt = (ch + 1) & 1;
        if (ch < 5) {
            OUT_PRODUCE_A(nxt, ch + 1)
            aux_copy_B_async(sm, nxt, ch + 1, tid, g_W2Thi, g_W2Tlo);
            cp_async_commit();
        }
        const uint32_t aHiL = smB + XOFF_AHI + cur * XAB + aLane;
        const uint32_t aLoL = smB + XOFF_ALO + cur * XAB + aLane;
        const uint32_t bHiA = smB + XOFF_BHI + cur * XBB + bLane;
        const uint32_t bLoA = smB + XOFF_BLO + cur * XBB + bLane;
        CONSUME_3T(3, aHiL, aLoL, bHiA, bLoA)
        if (ch < 5) cp_async_wait0();
        __syncthreads();
    }

    const int r_hi = s0 + wm * 16 + g;
#pragma unroll
    for (int in = 0; in < 6; ++in) {
        int c = wn * 48 + in * 8 + tg * 2;
        float2 bb = *(const float2*)&sB2[c];
        float2 v0 = {acc[in][0] + bb.x, acc[in][1] + bb.y};
        float2 v1 = {acc[in][2] + bb.x, acc[in][3] + bb.y};
        *(float2*)&out[r_hi * HIDDEN + c] = v0;
        *(float2*)&out[(r_hi + 8) * HIDDEN + c] = v1;
    }
}

// ============================================================
extern "C" void kernel_launch(void* const* d_in, const int* in_sizes, int n_in,
                              void* d_out, int out_size) {
    const float* feat = (const float*)d_in[0];
    const float* pos = (const float*)d_in[1];
    const int* src_idx = (const int*)d_in[2];
    const int* dst_idx = (const int*)d_in[3];
    const float* Win = (const float*)d_in[4];
    const float* bin = (const float*)d_in[5];
    const float* W1 = (const float*)d_in[6];
    const float* b1 = (const float*)d_in[7];
    const float* W2 = (const float*)d_in[8];
    const float* b2 = (const float*)d_in[9];
    float* out = (float*)d_out;

    const int E = in_sizes[2];
    const int S = E / MAXDEG;   // 8192

    static int smem_set = 0;
    if (!smem_set) {
        cudaFuncSetAttribute(snp_mma_kernel, cudaFuncAttributeMaxDynamicSharedMemorySize,
                             SMEMB_TOTAL);
        cudaFuncSetAttribute(dst_mma_kernel, cudaFuncAttributeMaxDynamicSharedMemorySize,
                             XSMEM_DST);
        cudaFuncSetAttribute(out_mma_kernel, cudaFuncAttributeMaxDynamicSharedMemorySize,
                             XSMEM_OUT);
        smem_set = 1;
    }

    weight_split_kernel<<<(HIDDEN * HIDDEN + 255) / 256, 256>>>(W1, W2);
    embed_kernel<<<(E * 8 + 255) / 256, 256>>>(feat, pos, src_idx, Win, bin, E);
    dst_mma_kernel<<<S / 32, 256, XSMEM_DST>>>(feat, pos, dst_idx, Win, bin, b1);
    snp_mma_kernel<<<S / 2, 512, SMEMB_TOTAL>>>();
    out_mma_kernel<<<S / 32, 256, XSMEM_OUT>>>(b2, out);
}

// round 16
// speedup vs baseline: 1.3716x; 1.3716x over previous
#include <cuda_runtime.h>
#include <cuda_bf16.h>
#include <cuda_fp16.h>
#include <cstdint>

#define HIDDEN 192
#define MAXDEG 32
#define MAX_S 8192

// scratch (device globals: allocation-free). 16B-aligned for vector ld/st + cp.async.
__device__ __align__(16) float g_dstpart[MAX_S * HIDDEN];         // b1 + x_dst @ W1_bot
__device__ __align__(16) float g_pooled[MAX_S * HIDDEN];          // mean(gelu(...))
__device__ __align__(16) __half g_W1Tf16[HIDDEN * HIDDEN];        // W1_top^T fp16 [n][k]
__device__ __align__(16) __nv_bfloat16 g_W1bThi[HIDDEN * HIDDEN]; // W1_bot^T hi
__device__ __align__(16) __nv_bfloat16 g_W1bTlo[HIDDEN * HIDDEN]; // W1_bot^T lo
__device__ __align__(16) __nv_bfloat16 g_W2Thi[HIDDEN * HIDDEN];  // W2^T hi
__device__ __align__(16) __nv_bfloat16 g_W2Tlo[HIDDEN * HIDDEN];  // W2^T lo

// ---------------- helpers ----------------
// branch-free GELU: A&S 7.1.26 erf (abs err <= 1.5e-7), MUFU rcp/ex2
__device__ __forceinline__ float gelu_fast(float x) {
    float z = fabsf(x) * 0.7071067811865476f;
    float d = fmaf(0.3275911f, z, 1.0f);
    float t;
    asm("rcp.approx.f32 %0, %1;" : "=f"(t) : "f"(d));
    float p = 1.061405429f;
    p = fmaf(p, t, -1.453152027f);
    p = fmaf(p, t, 1.421413741f);
    p = fmaf(p, t, -0.284496736f);
    p = fmaf(p, t, 0.254829592f);
    p = p * t;
    float y = -1.4426950408889634f * z * z;
    float e;
    asm("ex2.approx.f32 %0, %1;" : "=f"(e) : "f"(y));
    float erfv = fmaf(-p, e, 1.0f);
    erfv = copysignf(erfv, x);
    float hx = 0.5f * x;
    return fmaf(hx, erfv, hx);
}
// embed channel via MUFU sincos (abs err ~1e-6, angles in [0,1])
__device__ __forceinline__ float embed_channel(int c, float f0, float f1, float f2,
                                               const float* pp, const float* sWin,
                                               const float* sBin, const float* sOmega) {
    float v = sBin[c];
    v = fmaf(f0, sWin[c], v);
    v = fmaf(f1, sWin[HIDDEN + c], v);
    v = fmaf(f2, sWin[2 * HIDDEN + c], v);
    int axis = c >> 6;
    int j = c & 63;
    float ang = pp[axis] * sOmega[j & 31];
    float e;
    if (j < 32)
        asm("sin.approx.f32 %0, %1;" : "=f"(e) : "f"(ang));
    else
        asm("cos.approx.f32 %0, %1;" : "=f"(e) : "f"(ang));
    return v + e;
}
__device__ __forceinline__ void mma_bf16(float* c, uint32_t a0, uint32_t a1, uint32_t a2,
                                         uint32_t a3, uint32_t b0, uint32_t b1) {
    asm volatile(
        "mma.sync.aligned.m16n8k16.row.col.f32.bf16.bf16.f32 "
        "{%0,%1,%2,%3}, {%4,%5,%6,%7}, {%8,%9}, {%0,%1,%2,%3};"
        : "+f"(c[0]), "+f"(c[1]), "+f"(c[2]), "+f"(c[3])
        : "r"(a0), "r"(a1), "r"(a2), "r"(a3), "r"(b0), "r"(b1));
}
__device__ __forceinline__ void mma_f16(float* c, uint32_t a0, uint32_t a1, uint32_t a2,
                                        uint32_t a3, uint32_t b0, uint32_t b1) {
    asm volatile(
        "mma.sync.aligned.m16n8k16.row.col.f32.f16.f16.f32 "
        "{%0,%1,%2,%3}, {%4,%5,%6,%7}, {%8,%9}, {%0,%1,%2,%3};"
        : "+f"(c[0]), "+f"(c[1]), "+f"(c[2]), "+f"(c[3])
        : "r"(a0), "r"(a1), "r"(a2), "r"(a3), "r"(b0), "r"(b1));
}
__device__ __forceinline__ void ldsm_x4(uint32_t& r0, uint32_t& r1, uint32_t& r2,
                                        uint32_t& r3, uint32_t addr) {
    asm volatile("ldmatrix.sync.aligned.m8n8.x4.shared.b16 {%0,%1,%2,%3}, [%4];"
                 : "=r"(r0), "=r"(r1), "=r"(r2), "=r"(r3) : "r"(addr));
}
__device__ __forceinline__ uint32_t pack_bf16(float v0, float v1) {
    __nv_bfloat162 t;
    t.x = __float2bfloat16(v0);
    t.y = __float2bfloat16(v1);
    return *reinterpret_cast<uint32_t*>(&t);
}
__device__ __forceinline__ uint32_t pack_f16(float v0, float v1) {
    __half2 t;
    t.x = __float2half_rn(v0);
    t.y = __float2half_rn(v1);
    return *reinterpret_cast<uint32_t*>(&t);
}
__device__ __forceinline__ uint32_t smem_u32(const void* p) {
    uint32_t a;
    asm("{ .reg .u64 t; cvta.to.shared.u64 t, %1; cvt.u32.u64 %0, t; }" : "=r"(a) : "l"(p));
    return a;
}
__device__ __forceinline__ void cp_async16(void* dst_smem, const void* src) {
    uint32_t d = smem_u32(dst_smem);
    asm volatile("cp.async.cg.shared.global [%0], [%1], 16;" :: "r"(d), "l"(src) : "memory");
}
__device__ __forceinline__ void cp_async_commit() {
    asm volatile("cp.async.commit_group;" ::: "memory");
}
__device__ __forceinline__ void cp_async_wait0() {
    asm volatile("cp.async.wait_group 0;" ::: "memory");
}

#define STRIDE_A 80  // 16B-multiple (LDSM requirement), conflict-free
#define STRIDE_B 80

__device__ __forceinline__ uint32_t b_lane_off(int wn, int lane, int nw) {
    return (uint32_t)(wn * nw + ((lane >> 4) & 1) * 8 + (lane & 7)) * STRIDE_B +
           ((lane >> 3) & 1) * 16;
}
__device__ __forceinline__ uint32_t a_lane_off(int wm, int lane) {
    return (uint32_t)(wm * 16 + (lane & 15)) * STRIDE_A + ((lane >> 4) & 1) * 16;
}

// bf16 3-term consume, NP n-pairs, A/B via LDSM
#define CONSUME_3T(NP, aHiL, aLoL, bHiA, bLoA)                                           \
    _Pragma("unroll") for (int ks = 0; ks < 2; ++ks) {                                   \
        uint32_t ah0, ah1, ah2, ah3, al0, al1, al2, al3;                                 \
        ldsm_x4(ah0, ah1, ah2, ah3, (aHiL) + ks * 32);                                   \
        ldsm_x4(al0, al1, al2, al3, (aLoL) + ks * 32);                                   \
        _Pragma("unroll") for (int p = 0; p < (NP); ++p) {                               \
            uint32_t bh0, bh1, bh2, bh3, bl0, bl1, bl2, bl3;                             \
            ldsm_x4(bh0, bh1, bh2, bh3, (bHiA) + p * (16 * STRIDE_B) + ks * 32);         \
            ldsm_x4(bl0, bl1, bl2, bl3, (bLoA) + p * (16 * STRIDE_B) + ks * 32);         \
            mma_bf16(acc[2 * p], ah0, ah1, ah2, ah3, bh0, bh1);                          \
            mma_bf16(acc[2 * p], al0, al1, al2, al3, bh0, bh1);                          \
            mma_bf16(acc[2 * p], ah0, ah1, ah2, ah3, bl0, bl1);                          \
            mma_bf16(acc[2 * p + 1], ah0, ah1, ah2, ah3, bh2, bh3);                      \
            mma_bf16(acc[2 * p + 1], al0, al1, al2, al3, bh2, bh3);                      \
            mma_bf16(acc[2 * p + 1], ah0, ah1, ah2, ah3, bl2, bl3);                      \
        }                                                                                \
    }

// fp16 single-term consume (snp)
#define CONSUME_1T(NP, aHiL, bHiA)                                                       \
    _Pragma("unroll") for (int ks = 0; ks < 2; ++ks) {                                   \
        uint32_t ah0, ah1, ah2, ah3;                                                     \
        ldsm_x4(ah0, ah1, ah2, ah3, (aHiL) + ks * 32);                                   \
        _Pragma("unroll") for (int p = 0; p < (NP); ++p) {                               \
            uint32_t bh0, bh1, bh2, bh3;                                                 \
            ldsm_x4(bh0, bh1, bh2, bh3, (bHiA) + p * (16 * STRIDE_B) + ks * 32);         \
            mma_f16(acc[2 * p], ah0, ah1, ah2, ah3, bh0, bh1);                           \
            mma_f16(acc[2 * p + 1], ah0, ah1, ah2, ah3, bh2, bh3);                       \
        }                                                                                \
    }

// ============================================================
// Kernel P: W1_top^T -> fp16; W1_bot^T, W2^T -> bf16 hi/lo
// ============================================================
__global__ void __launch_bounds__(256)
weight_split_kernel(const float* __restrict__ W1, const float* __restrict__ W2) {
    int i = blockIdx.x * 256 + threadIdx.x;
    if (i >= HIDDEN * HIDDEN) return;
    int k = i / HIDDEN, n = i % HIDDEN;
    g_W1Tf16[n * HIDDEN + k] = __float2half_rn(W1[k * HIDDEN + n]);
    {
        float w = W1[(HIDDEN + k) * HIDDEN + n];
        __nv_bfloat16 hi = __float2bfloat16(w);
        g_W1bThi[n * HIDDEN + k] = hi;
        g_W1bTlo[n * HIDDEN + k] = __float2bfloat16(w - __bfloat162float(hi));
    }
    {
        float w = W2[k * HIDDEN + n];
        __nv_bfloat16 hi = __float2bfloat16(w);
        g_W2Thi[n * HIDDEN + k] = hi;
        g_W2Tlo[n * HIDDEN + k] = __float2bfloat16(w - __bfloat162float(hi));
    }
}

// ============================================================
// Kernels A/C: M=32/CTA, 256 thr, bf16 3-term, PIPELINED
// ============================================================
#define XAB (32 * STRIDE_A)
#define XBB (HIDDEN * STRIDE_B)
#define XOFF_AHI 0
#define XOFF_ALO (2 * XAB)
#define XOFF_BHI (4 * XAB)
#define XOFF_BLO (4 * XAB + 2 * XBB)
#define XOFF_CONST (4 * XAB + 4 * XBB)
#define XSMEM_DST (XOFF_CONST + 3 * HIDDEN * 4 + HIDDEN * 4 + 128 + HIDDEN * 4)
#define XSMEM_OUT (XOFF_CONST + HIDDEN * 4)

__device__ __forceinline__ void aux_copy_B_async(unsigned char* sm, int buf, int ch,
                                                 int tid, const __nv_bfloat16* Whi,
                                                 const __nv_bfloat16* Wlo) {
#pragma unroll
    for (int i = 0; i < 6; ++i) {
        int isLo = i >= 3;
        int id = tid + 256 * (isLo ? (i - 3) : i);
        int n = id >> 2, seg = id & 3;
        const __nv_bfloat16* src =
            (isLo ? Wlo : Whi) + n * HIDDEN + ch * 32 + seg * 8;
        unsigned char* dst = sm + (isLo ? XOFF_BLO : XOFF_BHI) + buf * XBB +
                             n * STRIDE_B + seg * 16;
        cp_async16(dst, src);
    }
}

__global__ void __launch_bounds__(256, 2)
dst_mma_kernel(const float* __restrict__ feat, const float* __restrict__ pos,
               const int* __restrict__ dst_idx, const float* __restrict__ Win,
               const float* __restrict__ bin, const float* __restrict__ b1) {
    extern __shared__ __align__(16) unsigned char sm[];
    float* sWin = (float*)(sm + XOFF_CONST);
    float* sBin = (float*)(sm + XOFF_CONST + 3 * HIDDEN * 4);
    float* sOmega = (float*)(sm + XOFF_CONST + 4 * HIDDEN * 4);
    float* sB1 = (float*)(sm + XOFF_CONST + 4 * HIDDEN * 4 + 128);

    const int tid = threadIdx.x;
    const int lane = tid & 31;
    const int w = tid >> 5;
    const int wm = w & 1, wn = w >> 1;
    const int g = lane >> 2, tg = lane & 3;
    const int s0 = blockIdx.x * 32;

    for (int i = tid; i < 3 * HIDDEN; i += 256) sWin[i] = Win[i];
    for (int i = tid; i < HIDDEN; i += 256) sBin[i] = bin[i];
    for (int i = tid; i < HIDDEN; i += 256) sB1[i] = b1[i];
    if (tid < 32) sOmega[tid] = exp2f(-(float)tid * 0.4152410118609203f);

    const int m = tid & 31;
    const int jb = (tid >> 5) * 4;
    int node = dst_idx[(s0 + m) * MAXDEG];
    float f0 = feat[node * 3], f1 = feat[node * 3 + 1], f2 = feat[node * 3 + 2];
    float pp[3] = {pos[node * 3], pos[node * 3 + 1], pos[node * 3 + 2]};
    __syncthreads();

    float acc[6][4];
#pragma unroll
    for (int i = 0; i < 6; ++i)
#pragma unroll
        for (int j = 0; j < 4; ++j) acc[i][j] = 0.0f;

    const uint32_t smB = smem_u32(sm);
    const uint32_t aLane = a_lane_off(wm, lane);
    const uint32_t bLane = b_lane_off(wn, lane, 48);

#define DST_PRODUCE_A(buf, ch)                                                           \
    _Pragma("unroll") for (int j = 0; j < 4; j += 2) {                                   \
        int c0 = (ch) * 32 + jb + j;                                                     \
        float v0 = embed_channel(c0, f0, f1, f2, pp, sWin, sBin, sOmega);                \
        float v1 = embed_channel(c0 + 1, f0, f1, f2, pp, sWin, sBin, sOmega);            \
        __nv_bfloat16 h0 = __float2bfloat16(v0);                                         \
        __nv_bfloat16 h1 = __float2bfloat16(v1);                                         \
        float l0 = v0 - __bfloat162float(h0);                                            \
        float l1 = v1 - __bfloat162float(h1);                                            \
        __nv_bfloat162 hp; hp.x = h0; hp.y = h1;                                         \
        *(uint32_t*)(sm + XOFF_AHI + (buf) * XAB + m * STRIDE_A + (jb + j) * 2) =        \
            *reinterpret_cast<uint32_t*>(&hp);                                           \
        *(uint32_t*)(sm + XOFF_ALO + (buf) * XAB + m * STRIDE_A + (jb + j) * 2) =        \
            pack_bf16(l0, l1);                                                           \
    }

    DST_PRODUCE_A(0, 0)
    aux_copy_B_async(sm, 0, 0, tid, g_W1bThi, g_W1bTlo);
    cp_async_commit();
    cp_async_wait0();
    __syncthreads();

    for (int ch = 0; ch < 6; ++ch) {
        const int cur = ch & 1;
        const int nxt = (ch + 1) & 1;
        if (ch < 5) {
            DST_PRODUCE_A(nxt, ch + 1)
            aux_copy_B_async(sm, nxt, ch + 1, tid, g_W1bThi, g_W1bTlo);
            cp_async_commit();
        }
        const uint32_t aHiL = smB + XOFF_AHI + cur * XAB + aLane;
        const uint32_t aLoL = smB + XOFF_ALO + cur * XAB + aLane;
        const uint32_t bHiA = smB + XOFF_BHI + cur * XBB + bLane;
        const uint32_t bLoA = smB + XOFF_BLO + cur * XBB + bLane;
        CONSUME_3T(3, aHiL, aLoL, bHiA, bLoA)
        if (ch < 5) cp_async_wait0();
        __syncthreads();
    }

    const int r_hi = s0 + wm * 16 + g;
#pragma unroll
    for (int in = 0; in < 6; ++in) {
        int c = wn * 48 + in * 8 + tg * 2;
        float2 bb = *(const float2*)&sB1[c];
        float2 v0 = {acc[in][0] + bb.x, acc[in][1] + bb.y};
        float2 v1 = {acc[in][2] + bb.x, acc[in][3] + bb.y};
        *(float2*)&g_dstpart[r_hi * HIDDEN + c] = v0;
        *(float2*)&g_dstpart[(r_hi + 8) * HIDDEN + c] = v1;
    }
}

// ============================================================
// Kernel B: pipelined snp_mma — fp16 1-term, 512 threads/16 warps
// ============================================================
#define AB (64 * STRIDE_A)        // 5120
#define BBUF (HIDDEN * STRIDE_B)  // 15360
#define OFF_AHI 0
#define OFF_BHI (2 * AB)
#define OFF_WIN (2 * AB + 2 * BBUF)
#define OFF_BIN (OFF_WIN + 3 * HIDDEN * 4)
#define OFF_OMG (OFF_BIN + HIDDEN * 4)
#define OFF_DST (OFF_OMG + 128)
#define OFF_COL (OFF_DST + 2 * HIDDEN * 4)
#define SMEMB_TOTAL (OFF_COL + 4 * HIDDEN * 4)   // 48768

__device__ __forceinline__ void produce_A4(unsigned char* aHi, int ch, int m, int jb,
                                           float f0, float f1, float f2, const float* pp,
                                           const float* sWin, const float* sBin,
                                           const float* sOmega) {
#pragma unroll
    for (int j = 0; j < 4; j += 2) {
        int c0 = ch * 32 + jb + j;
        float v0 = embed_channel(c0, f0, f1, f2, pp, sWin, sBin, sOmega);
        float v1 = embed_channel(c0 + 1, f0, f1, f2, pp, sWin, sBin, sOmega);
        *(uint32_t*)(aHi + m * STRIDE_A + (jb + j) * 2) = pack_f16(v0, v1);
    }
}

__device__ __forceinline__ void copy_B512(unsigned char* bHi, int ch, int tid) {
    {
        int id = tid;
        int n = id >> 2, seg = id & 3;
        cp_async16(bHi + n * STRIDE_B + seg * 16,
                   g_W1Tf16 + n * HIDDEN + ch * 32 + seg * 8);
    }
    if (tid < 256) {
        int id = tid + 512;
        int n = id >> 2, seg = id & 3;
        cp_async16(bHi + n * STRIDE_B + seg * 16,
                   g_W1Tf16 + n * HIDDEN + ch * 32 + seg * 8);
    }
}

__global__ void __launch_bounds__(512, 2)
snp_mma_kernel(const float* __restrict__ feat, const float* __restrict__ pos,
               const int* __restrict__ src_idx, const float* __restrict__ Win,
               const float* __restrict__ bin) {
    extern __shared__ __align__(16) unsigned char sm[];
    float* sWin = (float*)(sm + OFF_WIN);
    float* sBin = (float*)(sm + OFF_BIN);
    float* sOmega = (float*)(sm + OFF_OMG);
    float* sDst = (float*)(sm + OFF_DST);
    float* sCol = (float*)(sm + OFF_COL);

    const int b = blockIdx.x;
    const int tid = threadIdx.x;
    const int lane = tid & 31;
    const int w = tid >> 5;
    const int wm = w & 3, wn = w >> 2;
    const int g = lane >> 2, tg = lane & 3;

    for (int i = tid; i < 3 * HIDDEN; i += 512) sWin[i] = Win[i];
    for (int i = tid; i < HIDDEN; i += 512) sBin[i] = bin[i];
    for (int i = tid; i < 2 * HIDDEN; i += 512) sDst[i] = g_dstpart[b * 2 * HIDDEN + i];
    if (tid < 32) sOmega[tid] = exp2f(-(float)tid * 0.4152410118609203f);

    const int m = tid & 63;
    const int jb = (tid >> 6) * 4;
    int node = src_idx[b * 64 + m];
    float f0 = feat[node * 3], f1 = feat[node * 3 + 1], f2 = feat[node * 3 + 2];
    float pp[3] = {pos[node * 3], pos[node * 3 + 1], pos[node * 3 + 2]};
    __syncthreads();

    float acc[6][4];
#pragma unroll
    for (int i = 0; i < 6; ++i)
#pragma unroll
        for (int j = 0; j < 4; ++j) acc[i][j] = 0.0f;

    const uint32_t smB = smem_u32(sm);
    const uint32_t aLane = a_lane_off(wm, lane);
    const uint32_t bLane = b_lane_off(wn, lane, 48);

    produce_A4(sm + OFF_AHI, 0, m, jb, f0, f1, f2, pp, sWin, sBin, sOmega);
    copy_B512(sm + OFF_BHI, 0, tid);
    cp_async_commit();
    cp_async_wait0();
    __syncthreads();

    for (int c = 0; c < 6; ++c) {
        const int cur = c & 1;
        const int nxt = (c + 1) & 1;
        if (c < 5) {
            produce_A4(sm + OFF_AHI + nxt * AB, c + 1, m, jb, f0, f1, f2, pp, sWin, sBin,
                       sOmega);
            copy_B512(sm + OFF_BHI + nxt * BBUF, c + 1, tid);
            cp_async_commit();
        }

        const uint32_t aHiL = smB + OFF_AHI + cur * AB + aLane;
        const uint32_t bHiA = smB + OFF_BHI + cur * BBUF + bLane;
        CONSUME_1T(3, aHiL, bHiA)

        if (c < 5) cp_async_wait0();
        __syncthreads();
    }

    // epilogue: + dstpart, fast GELU, column sums
    const int sn = wm >> 1;
#pragma unroll
    for (int in = 0; in < 6; ++in) {
        int c = wn * 48 + in * 8 + tg * 2;
        float2 d = *(const float2*)&sDst[sn * HIDDEN + c];
        float t0 = gelu_fast(acc[in][0] + d.x) + gelu_fast(acc[in][2] + d.x);
        float t1 = gelu_fast(acc[in][1] + d.y) + gelu_fast(acc[in][3] + d.y);
#pragma unroll
        for (int off = 4; off < 32; off <<= 1) {
            t0 += __shfl_xor_sync(0xffffffffu, t0, off);
            t1 += __shfl_xor_sync(0xffffffffu, t1, off);
        }
        if (lane < 4) {
            sCol[wm * HIDDEN + c] = t0;
            sCol[wm * HIDDEN + c + 1] = t1;
        }
    }
    __syncthreads();
    for (int i = tid; i < 2 * HIDDEN; i += 512) {
        int s = i / HIDDEN, n = i % HIDDEN;
        g_pooled[(b * 2 + s) * HIDDEN + n] =
            (sCol[s * 2 * HIDDEN + n] + sCol[(s * 2 + 1) * HIDDEN + n]) * (1.0f / 32.0f);
    }
}

// ============================================================
// Kernel C: out = g_pooled @ W2 + b2, M=32/CTA, PIPELINED
// ============================================================
__global__ void __launch_bounds__(256, 2)
out_mma_kernel(const float* __restrict__ b2, float* __restrict__ out) {
    extern __shared__ __align__(16) unsigned char sm[];
    float* sB2 = (float*)(sm + XOFF_CONST);

    const int tid = threadIdx.x;
    const int lane = tid & 31;
    const int w = tid >> 5;
    const int wm = w & 1, wn = w >> 1;
    const int g = lane >> 2, tg = lane & 3;
    const int s0 = blockIdx.x * 32;

    for (int i = tid; i < HIDDEN; i += 256) sB2[i] = b2[i];

    const int m = tid & 31;
    const int jb = (tid >> 5) * 4;

    float acc[6][4];
#pragma unroll
    for (int i = 0; i < 6; ++i)
#pragma unroll
        for (int j = 0; j < 4; ++j) acc[i][j] = 0.0f;

    const uint32_t smB = smem_u32(sm);
    const uint32_t aLane = a_lane_off(wm, lane);
    const uint32_t bLane = b_lane_off(wn, lane, 48);

#define OUT_PRODUCE_A(buf, ch)                                                           \
    {                                                                                    \
        const float* arow = g_pooled + (s0 + m) * HIDDEN + (ch) * 32 + jb;               \
        _Pragma("unroll") for (int j = 0; j < 4; j += 2) {                               \
            float2 v = *(const float2*)&arow[j];                                         \
            __nv_bfloat16 h0 = __float2bfloat16(v.x);                                    \
            __nv_bfloat16 h1 = __float2bfloat16(v.y);                                    \
            float l0 = v.x - __bfloat162float(h0);                                       \
            float l1 = v.y - __bfloat162float(h1);                                       \
            __nv_bfloat162 hp; hp.x = h0; hp.y = h1;                                     \
            *(uint32_t*)(sm + XOFF_AHI + (buf) * XAB + m * STRIDE_A + (jb + j) * 2) =    \
                *reinterpret_cast<uint32_t*>(&hp);                                       \
            *(uint32_t*)(sm + XOFF_ALO + (buf) * XAB + m * STRIDE_A + (jb + j) * 2) =    \
                pack_bf16(l0, l1);                                                       \
        }                                                                                \
    }

    OUT_PRODUCE_A(0, 0)
    aux_copy_B_async(sm, 0, 0, tid, g_W2Thi, g_W2Tlo);
    cp_async_commit();
    cp_async_wait0();
    __syncthreads();

    for (int ch = 0; ch < 6; ++ch) {
        const int cur = ch & 1;
        const int nxt = (ch + 1) & 1;
        if (ch < 5) {
            OUT_PRODUCE_A(nxt, ch + 1)
            aux_copy_B_async(sm, nxt, ch + 1, tid, g_W2Thi, g_W2Tlo);
            cp_async_commit();
        }
        const uint32_t aHiL = smB + XOFF_AHI + cur * XAB + aLane;
        const uint32_t aLoL = smB + XOFF_ALO + cur * XAB + aLane;
        const uint32_t bHiA = smB + XOFF_BHI + cur * XBB + bLane;
        const uint32_t bLoA = smB + XOFF_BLO + cur * XBB + bLane;
        CONSUME_3T(3, aHiL, aLoL, bHiA, bLoA)
        if (ch < 5) cp_async_wait0();
        __syncthreads();
    }

    const int r_hi = s0 + wm * 16 + g;
#pragma unroll
    for (int in = 0; in < 6; ++in) {
        int c = wn * 48 + in * 8 + tg * 2;
        float2 bb = *(const float2*)&sB2[c];
        float2 v0 = {acc[in][0] + bb.x, acc[in][1] + bb.y};
        float2 v1 = {acc[in][2] + bb.x, acc[in][3] + bb.y};
        *(float2*)&out[r_hi * HIDDEN + c] = v0;
        *(float2*)&out[(r_hi + 8) * HIDDEN + c] = v1;
    }
}

// ============================================================
extern "C" void kernel_launch(void* const* d_in, const int* in_sizes, int n_in,
                              void* d_out, int out_size) {
    const float* feat = (const float*)d_in[0];
    const float* pos = (const float*)d_in[1];
    const int* src_idx = (const int*)d_in[2];
    const int* dst_idx = (const int*)d_in[3];
    const float* Win = (const float*)d_in[4];
    const float* bin = (const float*)d_in[5];
    const float* W1 = (const float*)d_in[6];
    const float* b1 = (const float*)d_in[7];
    const float* W2 = (const float*)d_in[8];
    const float* b2 = (const float*)d_in[9];
    float* out = (float*)d_out;

    const int E = in_sizes[2];
    const int S = E / MAXDEG;   // 8192

    static int smem_set = 0;
    if (!smem_set) {
        cudaFuncSetAttribute(snp_mma_kernel, cudaFuncAttributeMaxDynamicSharedMemorySize,
                             SMEMB_TOTAL);
        cudaFuncSetAttribute(dst_mma_kernel, cudaFuncAttributeMaxDynamicSharedMemorySize,
                             XSMEM_DST);
        cudaFuncSetAttribute(out_mma_kernel, cudaFuncAttributeMaxDynamicSharedMemorySize,
                             XSMEM_OUT);
        smem_set = 1;
    }

    weight_split_kernel<<<(HIDDEN * HIDDEN + 255) / 256, 256>>>(W1, W2);
    dst_mma_kernel<<<S / 32, 256, XSMEM_DST>>>(feat, pos, dst_idx, Win, bin, b1);
    snp_mma_kernel<<<S / 2, 512, SMEMB_TOTAL>>>(feat, pos, src_idx, Win, bin);
    out_mma_kernel<<<S / 32, 256, XSMEM_OUT>>>(b2, out);
}

// round 17
// speedup vs baseline: 1.3887x; 1.0125x over previous
#include <cuda_runtime.h>
#include <cuda_bf16.h>
#include <cuda_fp16.h>
#include <cstdint>

#define HIDDEN 192
#define MAXDEG 32
#define MAX_S 8192

// scratch (device globals: allocation-free). 16B-aligned for vector ld/st + cp.async.
__device__ __align__(16) float g_dstpart[MAX_S * HIDDEN];         // b1 + x_dst @ W1_bot
__device__ __align__(16) float g_pooled[MAX_S * HIDDEN];          // mean(gelu(...))
__device__ __align__(16) __half g_W1Tf16[HIDDEN * HIDDEN];        // W1_top^T fp16 [n][k]
__device__ __align__(16) __nv_bfloat16 g_W1bThi[HIDDEN * HIDDEN]; // W1_bot^T hi
__device__ __align__(16) __nv_bfloat16 g_W1bTlo[HIDDEN * HIDDEN]; // W1_bot^T lo
__device__ __align__(16) __nv_bfloat16 g_W2Thi[HIDDEN * HIDDEN];  // W2^T hi
__device__ __align__(16) __nv_bfloat16 g_W2Tlo[HIDDEN * HIDDEN];  // W2^T lo

// ---------------- helpers ----------------
__device__ __forceinline__ float gelu_fast(float x) {
    float z = fabsf(x) * 0.7071067811865476f;
    float d = fmaf(0.3275911f, z, 1.0f);
    float t;
    asm("rcp.approx.f32 %0, %1;" : "=f"(t) : "f"(d));
    float p = 1.061405429f;
    p = fmaf(p, t, -1.453152027f);
    p = fmaf(p, t, 1.421413741f);
    p = fmaf(p, t, -0.284496736f);
    p = fmaf(p, t, 0.254829592f);
    p = p * t;
    float y = -1.4426950408889634f * z * z;
    float e;
    asm("ex2.approx.f32 %0, %1;" : "=f"(e) : "f"(y));
    float erfv = fmaf(-p, e, 1.0f);
    erfv = copysignf(erfv, x);
    float hx = 0.5f * x;
    return fmaf(hx, erfv, hx);
}
// embed channel via MUFU sincos (abs err ~1e-6, angles in [0,1])
__device__ __forceinline__ float embed_channel(int c, float f0, float f1, float f2,
                                               const float* pp, const float* sWin,
                                               const float* sBin, const float* sOmega) {
    float v = sBin[c];
    v = fmaf(f0, sWin[c], v);
    v = fmaf(f1, sWin[HIDDEN + c], v);
    v = fmaf(f2, sWin[2 * HIDDEN + c], v);
    int axis = c >> 6;
    int j = c & 63;
    float ang = pp[axis] * sOmega[j & 31];
    float e;
    if (j < 32)
        asm("sin.approx.f32 %0, %1;" : "=f"(e) : "f"(ang));
    else
        asm("cos.approx.f32 %0, %1;" : "=f"(e) : "f"(ang));
    return v + e;
}
__device__ __forceinline__ void mma_bf16(float* c, uint32_t a0, uint32_t a1, uint32_t a2,
                                         uint32_t a3, uint32_t b0, uint32_t b1) {
    asm volatile(
        "mma.sync.aligned.m16n8k16.row.col.f32.bf16.bf16.f32 "
        "{%0,%1,%2,%3}, {%4,%5,%6,%7}, {%8,%9}, {%0,%1,%2,%3};"
        : "+f"(c[0]), "+f"(c[1]), "+f"(c[2]), "+f"(c[3])
        : "r"(a0), "r"(a1), "r"(a2), "r"(a3), "r"(b0), "r"(b1));
}
__device__ __forceinline__ void mma_f16(float* c, uint32_t a0, uint32_t a1, uint32_t a2,
                                        uint32_t a3, uint32_t b0, uint32_t b1) {
    asm volatile(
        "mma.sync.aligned.m16n8k16.row.col.f32.f16.f16.f32 "
        "{%0,%1,%2,%3}, {%4,%5,%6,%7}, {%8,%9}, {%0,%1,%2,%3};"
        : "+f"(c[0]), "+f"(c[1]), "+f"(c[2]), "+f"(c[3])
        : "r"(a0), "r"(a1), "r"(a2), "r"(a3), "r"(b0), "r"(b1));
}
__device__ __forceinline__ void ldsm_x4(uint32_t& r0, uint32_t& r1, uint32_t& r2,
                                        uint32_t& r3, uint32_t addr) {
    asm volatile("ldmatrix.sync.aligned.m8n8.x4.shared.b16 {%0,%1,%2,%3}, [%4];"
                 : "=r"(r0), "=r"(r1), "=r"(r2), "=r"(r3) : "r"(addr));
}
__device__ __forceinline__ uint32_t pack_bf16(float v0, float v1) {
    __nv_bfloat162 t;
    t.x = __float2bfloat16(v0);
    t.y = __float2bfloat16(v1);
    return *reinterpret_cast<uint32_t*>(&t);
}
__device__ __forceinline__ uint32_t pack_f16(float v0, float v1) {
    __half2 t;
    t.x = __float2half_rn(v0);
    t.y = __float2half_rn(v1);
    return *reinterpret_cast<uint32_t*>(&t);
}
__device__ __forceinline__ uint32_t smem_u32(const void* p) {
    uint32_t a;
    asm("{ .reg .u64 t; cvta.to.shared.u64 t, %1; cvt.u32.u64 %0, t; }" : "=r"(a) : "l"(p));
    return a;
}
__device__ __forceinline__ void cp_async16(void* dst_smem, const void* src) {
    uint32_t d = smem_u32(dst_smem);
    asm volatile("cp.async.cg.shared.global [%0], [%1], 16;" :: "r"(d), "l"(src) : "memory");
}
__device__ __forceinline__ void cp_async_commit() {
    asm volatile("cp.async.commit_group;" ::: "memory");
}
__device__ __forceinline__ void cp_async_wait0() {
    asm volatile("cp.async.wait_group 0;" ::: "memory");
}
__device__ __forceinline__ void cp_async_wait1() {
    asm volatile("cp.async.wait_group 1;" ::: "memory");
}

#define STRIDE_A 80  // 16B-multiple (LDSM requirement), conflict-free
#define STRIDE_B 80

__device__ __forceinline__ uint32_t b_lane_off(int wn, int lane, int nw) {
    return (uint32_t)(wn * nw + ((lane >> 4) & 1) * 8 + (lane & 7)) * STRIDE_B +
           ((lane >> 3) & 1) * 16;
}
__device__ __forceinline__ uint32_t a_lane_off(int wm, int lane) {
    return (uint32_t)(wm * 16 + (lane & 15)) * STRIDE_A + ((lane >> 4) & 1) * 16;
}

// bf16 3-term consume, NP n-pairs, A/B via LDSM
#define CONSUME_3T(NP, aHiL, aLoL, bHiA, bLoA)                                           \
    _Pragma("unroll") for (int ks = 0; ks < 2; ++ks) {                                   \
        uint32_t ah0, ah1, ah2, ah3, al0, al1, al2, al3;                                 \
        ldsm_x4(ah0, ah1, ah2, ah3, (aHiL) + ks * 32);                                   \
        ldsm_x4(al0, al1, al2, al3, (aLoL) + ks * 32);                                   \
        _Pragma("unroll") for (int p = 0; p < (NP); ++p) {                               \
            uint32_t bh0, bh1, bh2, bh3, bl0, bl1, bl2, bl3;                             \
            ldsm_x4(bh0, bh1, bh2, bh3, (bHiA) + p * (16 * STRIDE_B) + ks * 32);         \
            ldsm_x4(bl0, bl1, bl2, bl3, (bLoA) + p * (16 * STRIDE_B) + ks * 32);         \
            mma_bf16(acc[2 * p], ah0, ah1, ah2, ah3, bh0, bh1);                          \
            mma_bf16(acc[2 * p], al0, al1, al2, al3, bh0, bh1);                          \
            mma_bf16(acc[2 * p], ah0, ah1, ah2, ah3, bl0, bl1);                          \
            mma_bf16(acc[2 * p + 1], ah0, ah1, ah2, ah3, bh2, bh3);                      \
            mma_bf16(acc[2 * p + 1], al0, al1, al2, al3, bh2, bh3);                      \
            mma_bf16(acc[2 * p + 1], ah0, ah1, ah2, ah3, bl2, bl3);                      \
        }                                                                                \
    }

// fp16 single-term consume (snp)
#define CONSUME_1T(NP, aHiL, bHiA)                                                       \
    _Pragma("unroll") for (int ks = 0; ks < 2; ++ks) {                                   \
        uint32_t ah0, ah1, ah2, ah3;                                                     \
        ldsm_x4(ah0, ah1, ah2, ah3, (aHiL) + ks * 32);                                   \
        _Pragma("unroll") for (int p = 0; p < (NP); ++p) {                               \
            uint32_t bh0, bh1, bh2, bh3;                                                 \
            ldsm_x4(bh0, bh1, bh2, bh3, (bHiA) + p * (16 * STRIDE_B) + ks * 32);         \
            mma_f16(acc[2 * p], ah0, ah1, ah2, ah3, bh0, bh1);                           \
            mma_f16(acc[2 * p + 1], ah0, ah1, ah2, ah3, bh2, bh3);                       \
        }                                                                                \
    }

// ============================================================
// Kernel P: W1_top^T -> fp16; W1_bot^T, W2^T -> bf16 hi/lo
// ============================================================
__global__ void __launch_bounds__(256)
weight_split_kernel(const float* __restrict__ W1, const float* __restrict__ W2) {
    int i = blockIdx.x * 256 + threadIdx.x;
    if (i >= HIDDEN * HIDDEN) return;
    int k = i / HIDDEN, n = i % HIDDEN;
    g_W1Tf16[n * HIDDEN + k] = __float2half_rn(W1[k * HIDDEN + n]);
    {
        float w = W1[(HIDDEN + k) * HIDDEN + n];
        __nv_bfloat16 hi = __float2bfloat16(w);
        g_W1bThi[n * HIDDEN + k] = hi;
        g_W1bTlo[n * HIDDEN + k] = __float2bfloat16(w - __bfloat162float(hi));
    }
    {
        float w = W2[k * HIDDEN + n];
        __nv_bfloat16 hi = __float2bfloat16(w);
        g_W2Thi[n * HIDDEN + k] = hi;
        g_W2Tlo[n * HIDDEN + k] = __float2bfloat16(w - __bfloat162float(hi));
    }
}

// ============================================================
// Kernels A/C: M=32/CTA, 256 thr, bf16 3-term, PIPELINED (2-stage)
// ============================================================
#define XAB (32 * STRIDE_A)
#define XBB (HIDDEN * STRIDE_B)
#define XOFF_AHI 0
#define XOFF_ALO (2 * XAB)
#define XOFF_BHI (4 * XAB)
#define XOFF_BLO (4 * XAB + 2 * XBB)
#define XOFF_CONST (4 * XAB + 4 * XBB)
#define XSMEM_DST (XOFF_CONST + 3 * HIDDEN * 4 + HIDDEN * 4 + 128 + HIDDEN * 4)
#define XSMEM_OUT (XOFF_CONST + HIDDEN * 4)

__device__ __forceinline__ void aux_copy_B_async(unsigned char* sm, int buf, int ch,
                                                 int tid, const __nv_bfloat16* Whi,
                                                 const __nv_bfloat16* Wlo) {
#pragma unroll
    for (int i = 0; i < 6; ++i) {
        int isLo = i >= 3;
        int id = tid + 256 * (isLo ? (i - 3) : i);
        int n = id >> 2, seg = id & 3;
        const __nv_bfloat16* src =
            (isLo ? Wlo : Whi) + n * HIDDEN + ch * 32 + seg * 8;
        unsigned char* dst = sm + (isLo ? XOFF_BLO : XOFF_BHI) + buf * XBB +
                             n * STRIDE_B + seg * 16;
        cp_async16(dst, src);
    }
}

__global__ void __launch_bounds__(256, 2)
dst_mma_kernel(const float* __restrict__ feat, const float* __restrict__ pos,
               const int* __restrict__ dst_idx, const float* __restrict__ Win,
               const float* __restrict__ bin, const float* __restrict__ b1) {
    extern __shared__ __align__(16) unsigned char sm[];
    float* sWin = (float*)(sm + XOFF_CONST);
    float* sBin = (float*)(sm + XOFF_CONST + 3 * HIDDEN * 4);
    float* sOmega = (float*)(sm + XOFF_CONST + 4 * HIDDEN * 4);
    float* sB1 = (float*)(sm + XOFF_CONST + 4 * HIDDEN * 4 + 128);

    const int tid = threadIdx.x;
    const int lane = tid & 31;
    const int w = tid >> 5;
    const int wm = w & 1, wn = w >> 1;
    const int g = lane >> 2, tg = lane & 3;
    const int s0 = blockIdx.x * 32;

    for (int i = tid; i < 3 * HIDDEN; i += 256) sWin[i] = Win[i];
    for (int i = tid; i < HIDDEN; i += 256) sBin[i] = bin[i];
    for (int i = tid; i < HIDDEN; i += 256) sB1[i] = b1[i];
    if (tid < 32) sOmega[tid] = exp2f(-(float)tid * 0.4152410118609203f);

    const int m = tid & 31;
    const int jb = (tid >> 5) * 4;
    int node = dst_idx[(s0 + m) * MAXDEG];
    float f0 = feat[node * 3], f1 = feat[node * 3 + 1], f2 = feat[node * 3 + 2];
    float pp[3] = {pos[node * 3], pos[node * 3 + 1], pos[node * 3 + 2]};
    __syncthreads();

    float acc[6][4];
#pragma unroll
    for (int i = 0; i < 6; ++i)
#pragma unroll
        for (int j = 0; j < 4; ++j) acc[i][j] = 0.0f;

    const uint32_t smB = smem_u32(sm);
    const uint32_t aLane = a_lane_off(wm, lane);
    const uint32_t bLane = b_lane_off(wn, lane, 48);

#define DST_PRODUCE_A(buf, ch)                                                           \
    _Pragma("unroll") for (int j = 0; j < 4; j += 2) {                                   \
        int c0 = (ch) * 32 + jb + j;                                                     \
        float v0 = embed_channel(c0, f0, f1, f2, pp, sWin, sBin, sOmega);                \
        float v1 = embed_channel(c0 + 1, f0, f1, f2, pp, sWin, sBin, sOmega);            \
        __nv_bfloat16 h0 = __float2bfloat16(v0);                                         \
        __nv_bfloat16 h1 = __float2bfloat16(v1);                                         \
        float l0 = v0 - __bfloat162float(h0);                                            \
        float l1 = v1 - __bfloat162float(h1);                                            \
        __nv_bfloat162 hp; hp.x = h0; hp.y = h1;                                         \
        *(uint32_t*)(sm + XOFF_AHI + (buf) * XAB + m * STRIDE_A + (jb + j) * 2) =        \
            *reinterpret_cast<uint32_t*>(&hp);                                           \
        *(uint32_t*)(sm + XOFF_ALO + (buf) * XAB + m * STRIDE_A + (jb + j) * 2) =        \
            pack_bf16(l0, l1);                                                           \
    }

    DST_PRODUCE_A(0, 0)
    aux_copy_B_async(sm, 0, 0, tid, g_W1bThi, g_W1bTlo);
    cp_async_commit();
    cp_async_wait0();
    __syncthreads();

    for (int ch = 0; ch < 6; ++ch) {
        const int cur = ch & 1;
        const int nxt = (ch + 1) & 1;
        if (ch < 5) {
            DST_PRODUCE_A(nxt, ch + 1)
            aux_copy_B_async(sm, nxt, ch + 1, tid, g_W1bThi, g_W1bTlo);
            cp_async_commit();
        }
        const uint32_t aHiL = smB + XOFF_AHI + cur * XAB + aLane;
        const uint32_t aLoL = smB + XOFF_ALO + cur * XAB + aLane;
        const uint32_t bHiA = smB + XOFF_BHI + cur * XBB + bLane;
        const uint32_t bLoA = smB + XOFF_BLO + cur * XBB + bLane;
        CONSUME_3T(3, aHiL, aLoL, bHiA, bLoA)
        if (ch < 5) cp_async_wait0();
        __syncthreads();
    }

    const int r_hi = s0 + wm * 16 + g;
#pragma unroll
    for (int in = 0; in < 6; ++in) {
        int c = wn * 48 + in * 8 + tg * 2;
        float2 bb = *(const float2*)&sB1[c];
        float2 v0 = {acc[in][0] + bb.x, acc[in][1] + bb.y};
        float2 v1 = {acc[in][2] + bb.x, acc[in][3] + bb.y};
        *(float2*)&g_dstpart[r_hi * HIDDEN + c] = v0;
        *(float2*)&g_dstpart[(r_hi + 8) * HIDDEN + c] = v1;
    }
}

// ============================================================
// Kernel B: snp_mma — fp16 1-term, 512 threads, TRIPLE-buffered
// (prefetch distance 2: cp.async gets 2 consume phases to land)
// ============================================================
#define AB (64 * STRIDE_A)        // 5120
#define BBUF (HIDDEN * STRIDE_B)  // 15360
#define OFF_AHI 0                        // 3 bufs: 15360
#define OFF_BHI (3 * AB)                 // 3 bufs: 46080
#define OFF_WIN (3 * AB + 3 * BBUF)      // 61440
#define OFF_BIN (OFF_WIN + 3 * HIDDEN * 4)
#define OFF_OMG (OFF_BIN + HIDDEN * 4)
#define OFF_DST (OFF_OMG + 128)
#define OFF_COL (OFF_DST + 2 * HIDDEN * 4)
#define SMEMB_TOTAL (OFF_COL + 4 * HIDDEN * 4)   // 68736

__device__ __forceinline__ void produce_A4(unsigned char* aHi, int ch, int m, int jb,
                                           float f0, float f1, float f2, const float* pp,
                                           const float* sWin, const float* sBin,
                                           const float* sOmega) {
#pragma unroll
    for (int j = 0; j < 4; j += 2) {
        int c0 = ch * 32 + jb + j;
        float v0 = embed_channel(c0, f0, f1, f2, pp, sWin, sBin, sOmega);
        float v1 = embed_channel(c0 + 1, f0, f1, f2, pp, sWin, sBin, sOmega);
        *(uint32_t*)(aHi + m * STRIDE_A + (jb + j) * 2) = pack_f16(v0, v1);
    }
}

__device__ __forceinline__ void copy_B512(unsigned char* bHi, int ch, int tid) {
    {
        int id = tid;
        int n = id >> 2, seg = id & 3;
        cp_async16(bHi + n * STRIDE_B + seg * 16,
                   g_W1Tf16 + n * HIDDEN + ch * 32 + seg * 8);
    }
    if (tid < 256) {
        int id = tid + 512;
        int n = id >> 2, seg = id & 3;
        cp_async16(bHi + n * STRIDE_B + seg * 16,
                   g_W1Tf16 + n * HIDDEN + ch * 32 + seg * 8);
    }
}

__global__ void __launch_bounds__(512, 2)
snp_mma_kernel(const float* __restrict__ feat, const float* __restrict__ pos,
               const int* __restrict__ src_idx, const float* __restrict__ Win,
               const float* __restrict__ bin) {
    extern __shared__ __align__(16) unsigned char sm[];
    float* sWin = (float*)(sm + OFF_WIN);
    float* sBin = (float*)(sm + OFF_BIN);
    float* sOmega = (float*)(sm + OFF_OMG);
    float* sDst = (float*)(sm + OFF_DST);
    float* sCol = (float*)(sm + OFF_COL);

    const int b = blockIdx.x;
    const int tid = threadIdx.x;
    const int lane = tid & 31;
    const int w = tid >> 5;
    const int wm = w & 3, wn = w >> 2;
    const int g = lane >> 2, tg = lane & 3;

    for (int i = tid; i < 3 * HIDDEN; i += 512) sWin[i] = Win[i];
    for (int i = tid; i < HIDDEN; i += 512) sBin[i] = bin[i];
    for (int i = tid; i < 2 * HIDDEN; i += 512) sDst[i] = g_dstpart[b * 2 * HIDDEN + i];
    if (tid < 32) sOmega[tid] = exp2f(-(float)tid * 0.4152410118609203f);

    const int m = tid & 63;
    const int jb = (tid >> 6) * 4;
    int node = src_idx[b * 64 + m];
    float f0 = feat[node * 3], f1 = feat[node * 3 + 1], f2 = feat[node * 3 + 2];
    float pp[3] = {pos[node * 3], pos[node * 3 + 1], pos[node * 3 + 2]};
    __syncthreads();   // consts ready before produce reads them

    float acc[6][4];
#pragma unroll
    for (int i = 0; i < 6; ++i)
#pragma unroll
        for (int j = 0; j < 4; ++j) acc[i][j] = 0.0f;

    const uint32_t smB = smem_u32(sm);
    const uint32_t aLane = a_lane_off(wm, lane);
    const uint32_t bLane = b_lane_off(wn, lane, 48);

    // ---- prologue: stage chunks 0 and 1 (groups g0, g1) ----
    produce_A4(sm + OFF_AHI + 0 * AB, 0, m, jb, f0, f1, f2, pp, sWin, sBin, sOmega);
    copy_B512(sm + OFF_BHI + 0 * BBUF, 0, tid);
    cp_async_commit();
    produce_A4(sm + OFF_AHI + 1 * AB, 1, m, jb, f0, f1, f2, pp, sWin, sBin, sOmega);
    copy_B512(sm + OFF_BHI + 1 * BBUF, 1, tid);
    cp_async_commit();
    cp_async_wait1();   // g0 retired -> chunk 0 data in smem
    __syncthreads();

    // ---- 3-stage pipelined main loop ----
    for (int c = 0; c < 6; ++c) {
        const int cur = c % 3;
        if (c + 2 < 6) {
            const int pf = (c + 2) % 3;   // == (c-1)%3: consumed & fenced last iter
            produce_A4(sm + OFF_AHI + pf * AB, c + 2, m, jb, f0, f1, f2, pp, sWin, sBin,
                       sOmega);
            copy_B512(sm + OFF_BHI + pf * BBUF, c + 2, tid);
            cp_async_commit();
        }

        const uint32_t aHiL = smB + OFF_AHI + cur * AB + aLane;
        const uint32_t bHiA = smB + OFF_BHI + cur * BBUF + bLane;
        CONSUME_1T(3, aHiL, bHiA)

        // retire chunk c+1's group before next iteration consumes it
        if (c < 4)
            cp_async_wait1();
        else if (c == 4)
            cp_async_wait0();
        __syncthreads();
    }

    // ---- epilogue: + dstpart, fast GELU, column sums ----
    const int sn = wm >> 1;
#pragma unroll
    for (int in = 0; in < 6; ++in) {
        int c = wn * 48 + in * 8 + tg * 2;
        float2 d = *(const float2*)&sDst[sn * HIDDEN + c];
        float t0 = gelu_fast(acc[in][0] + d.x) + gelu_fast(acc[in][2] + d.x);
        float t1 = gelu_fast(acc[in][1] + d.y) + gelu_fast(acc[in][3] + d.y);
#pragma unroll
        for (int off = 4; off < 32; off <<= 1) {
            t0 += __shfl_xor_sync(0xffffffffu, t0, off);
            t1 += __shfl_xor_sync(0xffffffffu, t1, off);
        }
        if (lane < 4) {
            sCol[wm * HIDDEN + c] = t0;
            sCol[wm * HIDDEN + c + 1] = t1;
        }
    }
    __syncthreads();
    for (int i = tid; i < 2 * HIDDEN; i += 512) {
        int s = i / HIDDEN, n = i % HIDDEN;
        g_pooled[(b * 2 + s) * HIDDEN + n] =
            (sCol[s * 2 * HIDDEN + n] + sCol[(s * 2 + 1) * HIDDEN + n]) * (1.0f / 32.0f);
    }
}

// ============================================================
// Kernel C: out = g_pooled @ W2 + b2, M=32/CTA, PIPELINED
// ============================================================
__global__ void __launch_bounds__(256, 2)
out_mma_kernel(const float* __restrict__ b2, float* __restrict__ out) {
    extern __shared__ __align__(16) unsigned char sm[];
    float* sB2 = (float*)(sm + XOFF_CONST);

    const int tid = threadIdx.x;
    const int lane = tid & 31;
    const int w = tid >> 5;
    const int wm = w & 1, wn = w >> 1;
    const int g = lane >> 2, tg = lane & 3;
    const int s0 = blockIdx.x * 32;

    for (int i = tid; i < HIDDEN; i += 256) sB2[i] = b2[i];

    const int m = tid & 31;
    const int jb = (tid >> 5) * 4;

    float acc[6][4];
#pragma unroll
    for (int i = 0; i < 6; ++i)
#pragma unroll
        for (int j = 0; j < 4; ++j) acc[i][j] = 0.0f;

    const uint32_t smB = smem_u32(sm);
    const uint32_t aLane = a_lane_off(wm, lane);
    const uint32_t bLane = b_lane_off(wn, lane, 48);

#define OUT_PRODUCE_A(buf, ch)                                                           \
    {                                                                                    \
        const float* arow = g_pooled + (s0 + m) * HIDDEN + (ch) * 32 + jb;               \
        _Pragma("unroll") for (int j = 0; j < 4; j += 2) {                               \
            float2 v = *(const float2*)&arow[j];                                         \
            __nv_bfloat16 h0 = __float2bfloat16(v.x);                                    \
            __nv_bfloat16 h1 = __float2bfloat16(v.y);                                    \
            float l0 = v.x - __bfloat162float(h0);                                       \
            float l1 = v.y - __bfloat162float(h1);                                       \
            __nv_bfloat162 hp; hp.x = h0; hp.y = h1;                                     \
            *(uint32_t*)(sm + XOFF_AHI + (buf) * XAB + m * STRIDE_A + (jb + j) * 2) =    \
                *reinterpret_cast<uint32_t*>(&hp);                                       \
            *(uint32_t*)(sm + XOFF_ALO + (buf) * XAB + m * STRIDE_A + (jb + j) * 2) =    \
                pack_bf16(l0, l1);                                                       \
        }                                                                                \
    }

    OUT_PRODUCE_A(0, 0)
    aux_copy_B_async(sm, 0, 0, tid, g_W2Thi, g_W2Tlo);
    cp_async_commit();
    cp_async_wait0();
    __syncthreads();

    for (int ch = 0; ch < 6; ++ch) {
        const int cur = ch & 1;
        const int nxt = (ch + 1) & 1;
        if (ch < 5) {
            OUT_PRODUCE_A(nxt, ch + 1)
            aux_copy_B_async(sm, nxt, ch + 1, tid, g_W2Thi, g_W2Tlo);
            cp_async_commit();
        }
        const uint32_t aHiL = smB + XOFF_AHI + cur * XAB + aLane;
        const uint32_t aLoL = smB + XOFF_ALO + cur * XAB + aLane;
        const uint32_t bHiA = smB + XOFF_BHI + cur * XBB + bLane;
        const uint32_t bLoA = smB + XOFF_BLO + cur * XBB + bLane;
        CONSUME_3T(3, aHiL, aLoL, bHiA, bLoA)
        if (ch < 5) cp_async_wait0();
        __syncthreads();
    }

    const int r_hi = s0 + wm * 16 + g;
#pragma unroll
    for (int in = 0; in < 6; ++in) {
        int c = wn * 48 + in * 8 + tg * 2;
        float2 bb = *(const float2*)&sB2[c];
        float2 v0 = {acc[in][0] + bb.x, acc[in][1] + bb.y};
        float2 v1 = {acc[in][2] + bb.x, acc[in][3] + bb.y};
        *(float2*)&out[r_hi * HIDDEN + c] = v0;
        *(float2*)&out[(r_hi + 8) * HIDDEN + c] = v1;
    }
}

// ============================================================
extern "C" void kernel_launch(void* const* d_in, const int* in_sizes, int n_in,
                              void* d_out, int out_size) {
    const float* feat = (const float*)d_in[0];
    const float* pos = (const float*)d_in[1];
    const int* src_idx = (const int*)d_in[2];
    const int* dst_idx = (const int*)d_in[3];
    const float* Win = (const float*)d_in[4];
    const float* bin = (const float*)d_in[5];
    const float* W1 = (const float*)d_in[6];
    const float* b1 = (const float*)d_in[7];
    const float* W2 = (const float*)d_in[8];
    const float* b2 = (const float*)d_in[9];
    float* out = (float*)d_out;

    const int E = in_sizes[2];
    const int S = E / MAXDEG;   // 8192

    static int smem_set = 0;
    if (!smem_set) {
        cudaFuncSetAttribute(snp_mma_kernel, cudaFuncAttributeMaxDynamicSharedMemorySize,
                             SMEMB_TOTAL);
        cudaFuncSetAttribute(dst_mma_kernel, cudaFuncAttributeMaxDynamicSharedMemorySize,
                             XSMEM_DST);
        cudaFuncSetAttribute(out_mma_kernel, cudaFuncAttributeMaxDynamicSharedMemorySize,
                             XSMEM_OUT);
        smem_set = 1;
    }

    weight_split_kernel<<<(HIDDEN * HIDDEN + 255) / 256, 256>>>(W1, W2);
    dst_mma_kernel<<<S / 32, 256, XSMEM_DST>>>(feat, pos, dst_idx, Win, bin, b1);
    snp_mma_kernel<<<S / 2, 512, SMEMB_TOTAL>>>(feat, pos, src_idx, Win, bin);
    out_mma_kernel<<<S / 32, 256, XSMEM_OUT>>>(b2, out);
}